// round 1
// baseline (speedup 1.0000x reference)
#include <cuda_runtime.h>
#include <cstddef>

#define HD 128

// ---------------- scratch (device globals; no allocation allowed) ----------
__device__ float g_hcol [500000 * 128];
__device__ float g_hfilt[250000 * 128];
__device__ float g_hpred[100000 * 128];
__device__ float g_hscan[ 50000 * 128];
__device__ float g_hjoin[ 25000 * 128];
__device__ float g_henc [ 16384 * 128];
__device__ float g_msg  [250000 * 128];   // max N_dst = 250000

// ---------------- encoder: out = relu(x[N,32] @ W[32,128] + b) -------------
__global__ __launch_bounds__(128) void enc_kernel(
    const float* __restrict__ x, const float* __restrict__ W,
    const float* __restrict__ b, float* __restrict__ out, int N)
{
    const int BN = 32;
    __shared__ float s_x[BN][32];
    int base = blockIdx.x * BN;
    int t = threadIdx.x;

    // stage X tile (32 nodes x 32 feats) as float4
    for (int i = t; i < BN * 8; i += 128) {
        int n = i >> 3, c4 = (i & 7) * 4;
        float4 v = make_float4(0.f, 0.f, 0.f, 0.f);
        if (base + n < N) v = *(const float4*)(x + (size_t)(base + n) * 32 + c4);
        *(float4*)&s_x[n][c4] = v;
    }
    __syncthreads();

    float acc[BN];
    float bb = b[t];
#pragma unroll
    for (int n = 0; n < BN; n++) acc[n] = bb;

#pragma unroll
    for (int k0 = 0; k0 < 32; k0 += 4) {
        float w0 = W[(k0 + 0) * HD + t];
        float w1 = W[(k0 + 1) * HD + t];
        float w2 = W[(k0 + 2) * HD + t];
        float w3 = W[(k0 + 3) * HD + t];
#pragma unroll
        for (int n = 0; n < BN; n++) {
            float4 s = *(const float4*)&s_x[n][k0];  // broadcast LDS.128
            acc[n] = fmaf(s.x, w0, acc[n]);
            acc[n] = fmaf(s.y, w1, acc[n]);
            acc[n] = fmaf(s.z, w2, acc[n]);
            acc[n] = fmaf(s.w, w3, acc[n]);
        }
    }
    for (int n = 0; n < BN; n++)
        if (base + n < N) out[(size_t)(base + n) * HD + t] = fmaxf(acc[n], 0.f);
}

// ---------------- edge scatter: msg[dst[e]] += h_src[src[e]] ---------------
__global__ __launch_bounds__(256) void scatter_kernel(
    const float* __restrict__ h_src, const int* __restrict__ src,
    const int* __restrict__ dst, float* __restrict__ msg, int E)
{
    int e = blockIdx.x * (blockDim.x >> 5) + (threadIdx.x >> 5);
    if (e >= E) return;
    int lane = threadIdx.x & 31;
    int s = src[e];
    int d = dst[e];
    float4 v = *(const float4*)(h_src + (size_t)s * HD + lane * 4);
    float* p = msg + (size_t)d * HD + lane * 4;
    atomicAdd(p + 0, v.x);
    atomicAdd(p + 1, v.y);
    atomicAdd(p + 2, v.z);
    atomicAdd(p + 3, v.w);
}

// ------- tree MLP: h = relu(relu([h|msg] @ W1 + b1) @ W2 + b2), in place ----
__global__ __launch_bounds__(128) void tree_mlp_kernel(
    float* __restrict__ h_dst, const float* __restrict__ msg,
    const float* __restrict__ W1, const float* __restrict__ b1,
    const float* __restrict__ W2, const float* __restrict__ b2, int N)
{
    const int BN = 16;
    __shared__ float s_in[BN][256];  // [h_dst | msg]
    __shared__ float s_z[BN][128];
    int base = blockIdx.x * BN;
    int t = threadIdx.x;

    // stage concat tile: 16 nodes x (128 + 128) floats, float4 granularity
    for (int i = t; i < BN * 32; i += 128) {
        int n = i >> 5, c4 = (i & 31) * 4;
        float4 a = make_float4(0.f, 0.f, 0.f, 0.f);
        float4 m = make_float4(0.f, 0.f, 0.f, 0.f);
        if (base + n < N) {
            a = *(const float4*)(h_dst + (size_t)(base + n) * HD + c4);
            m = *(const float4*)(msg   + (size_t)(base + n) * HD + c4);
        }
        *(float4*)&s_in[n][c4]       = a;
        *(float4*)&s_in[n][128 + c4] = m;
    }
    __syncthreads();

    // layer 1: z[n][t] = relu(sum_k s_in[n][k] * W1[k][t] + b1[t])
    float acc[BN];
    {
        float bb = b1[t];
#pragma unroll
        for (int n = 0; n < BN; n++) acc[n] = bb;
#pragma unroll 4
        for (int k0 = 0; k0 < 256; k0 += 4) {
            float w0 = W1[(k0 + 0) * HD + t];
            float w1 = W1[(k0 + 1) * HD + t];
            float w2 = W1[(k0 + 2) * HD + t];
            float w3 = W1[(k0 + 3) * HD + t];
#pragma unroll
            for (int n = 0; n < BN; n++) {
                float4 s = *(const float4*)&s_in[n][k0];
                acc[n] = fmaf(s.x, w0, acc[n]);
                acc[n] = fmaf(s.y, w1, acc[n]);
                acc[n] = fmaf(s.z, w2, acc[n]);
                acc[n] = fmaf(s.w, w3, acc[n]);
            }
        }
#pragma unroll
        for (int n = 0; n < BN; n++) s_z[n][t] = fmaxf(acc[n], 0.f);
    }
    __syncthreads();

    // layer 2: out[n][t] = relu(sum_k z[n][k] * W2[k][t] + b2[t])
    {
        float bb = b2[t];
#pragma unroll
        for (int n = 0; n < BN; n++) acc[n] = bb;
#pragma unroll 4
        for (int k0 = 0; k0 < 128; k0 += 4) {
            float w0 = W2[(k0 + 0) * HD + t];
            float w1 = W2[(k0 + 1) * HD + t];
            float w2 = W2[(k0 + 2) * HD + t];
            float w3 = W2[(k0 + 3) * HD + t];
#pragma unroll
            for (int n = 0; n < BN; n++) {
                float4 s = *(const float4*)&s_z[n][k0];
                acc[n] = fmaf(s.x, w0, acc[n]);
                acc[n] = fmaf(s.y, w1, acc[n]);
                acc[n] = fmaf(s.z, w2, acc[n]);
                acc[n] = fmaf(s.w, w3, acc[n]);
            }
        }
        for (int n = 0; n < BN; n++)
            if (base + n < N) h_dst[(size_t)(base + n) * HD + t] = fmaxf(acc[n], 0.f);
    }
}

// ------- head: out[n] = relu(h @ Wf1 + bf1) @ Wf2 + bf2 --------------------
__global__ __launch_bounds__(128) void final_kernel(
    const float* __restrict__ h, const float* __restrict__ Wf1,
    const float* __restrict__ bf1, const float* __restrict__ Wf2,
    const float* __restrict__ bf2, float* __restrict__ out, int N)
{
    const int BN = 16;
    __shared__ float s_in[BN][128];
    __shared__ float s_z[BN][129];   // padded: conflict-free row dots below
    int base = blockIdx.x * BN;
    int t = threadIdx.x;

    for (int i = t; i < BN * 32; i += 128) {
        int n = i >> 5, c4 = (i & 31) * 4;
        float4 a = make_float4(0.f, 0.f, 0.f, 0.f);
        if (base + n < N) a = *(const float4*)(h + (size_t)(base + n) * HD + c4);
        *(float4*)&s_in[n][c4] = a;
    }
    __syncthreads();

    float acc[BN];
    float bb = bf1[t];
#pragma unroll
    for (int n = 0; n < BN; n++) acc[n] = bb;
#pragma unroll 4
    for (int k0 = 0; k0 < 128; k0 += 4) {
        float w0 = Wf1[(k0 + 0) * HD + t];
        float w1 = Wf1[(k0 + 1) * HD + t];
        float w2 = Wf1[(k0 + 2) * HD + t];
        float w3 = Wf1[(k0 + 3) * HD + t];
#pragma unroll
        for (int n = 0; n < BN; n++) {
            float4 s = *(const float4*)&s_in[n][k0];
            acc[n] = fmaf(s.x, w0, acc[n]);
            acc[n] = fmaf(s.y, w1, acc[n]);
            acc[n] = fmaf(s.z, w2, acc[n]);
            acc[n] = fmaf(s.w, w3, acc[n]);
        }
    }
#pragma unroll
    for (int n = 0; n < BN; n++) s_z[n][t] = fmaxf(acc[n], 0.f);
    __syncthreads();

    if (t < BN && base + t < N) {
        float a = bf2[0];
#pragma unroll 4
        for (int k = 0; k < 128; k++) a = fmaf(s_z[t][k], Wf2[k], a);
        out[base + t] = a;
    }
}

// ---------------------------------------------------------------------------
extern "C" void kernel_launch(void* const* d_in, const int* in_sizes, int n_in,
                              void* d_out, int out_size)
{
    const float* xs[6] = {
        (const float*)d_in[0], (const float*)d_in[1], (const float*)d_in[2],
        (const float*)d_in[3], (const float*)d_in[4], (const float*)d_in[5]
    };
    const float* W_enc = (const float*)d_in[6];
    const float* b_enc = (const float*)d_in[7];
    const float* W1    = (const float*)d_in[8];
    const float* b1    = (const float*)d_in[9];
    const float* W2    = (const float*)d_in[10];
    const float* b2    = (const float*)d_in[11];
    const float* Wf1   = (const float*)d_in[12];
    const float* bf1   = (const float*)d_in[13];
    const float* Wf2   = (const float*)d_in[14];
    const float* bf2   = (const float*)d_in[15];
    const int* esrc[5] = { (const int*)d_in[16], (const int*)d_in[18],
                           (const int*)d_in[20], (const int*)d_in[22],
                           (const int*)d_in[24] };
    const int* edst[5] = { (const int*)d_in[17], (const int*)d_in[19],
                           (const int*)d_in[21], (const int*)d_in[23],
                           (const int*)d_in[25] };
    int E[5] = { in_sizes[16], in_sizes[18], in_sizes[20], in_sizes[22], in_sizes[24] };
    int Nn[6];
    for (int i = 0; i < 6; i++) Nn[i] = in_sizes[i] / 32;

    float *hb[6], *msg;
    cudaGetSymbolAddress((void**)&hb[0], g_hcol);
    cudaGetSymbolAddress((void**)&hb[1], g_hfilt);
    cudaGetSymbolAddress((void**)&hb[2], g_hpred);
    cudaGetSymbolAddress((void**)&hb[3], g_hscan);
    cudaGetSymbolAddress((void**)&hb[4], g_hjoin);
    cudaGetSymbolAddress((void**)&hb[5], g_henc);
    cudaGetSymbolAddress((void**)&msg,   g_msg);

    // 1) node-type encoders
    for (int i = 0; i < 6; i++) {
        int grid = (Nn[i] + 31) / 32;
        enc_kernel<<<grid, 128>>>(xs[i], W_enc + (size_t)i * 32 * HD,
                                  b_enc + (size_t)i * HD, hb[i], Nn[i]);
    }

    // 2) five bottom-up levels: src hb[l] -> dst hb[l+1]
    for (int l = 0; l < 5; l++) {
        int Ndst = Nn[l + 1];
        cudaMemsetAsync(msg, 0, (size_t)Ndst * HD * sizeof(float));
        int sgrid = (E[l] + 7) / 8;  // 8 warps / block
        scatter_kernel<<<sgrid, 256>>>(hb[l], esrc[l], edst[l], msg, E[l]);
        int mgrid = (Ndst + 15) / 16;
        tree_mlp_kernel<<<mgrid, 128>>>(hb[l + 1], msg,
                                        W1 + (size_t)l * 256 * HD, b1 + (size_t)l * HD,
                                        W2 + (size_t)l * HD * HD,  b2 + (size_t)l * HD,
                                        Ndst);
    }

    // 3) head -> d_out [N_ENC, 1]
    {
        int grid = (Nn[5] + 15) / 16;
        final_kernel<<<grid, 128>>>(hb[5], Wf1, bf1, Wf2, bf2, (float*)d_out, Nn[5]);
    }
}